// round 2
// baseline (speedup 1.0000x reference)
#include <cuda_runtime.h>
#include <math.h>

#define B_   8
#define CF_  64
#define HW_  65536
#define HID_ 512
#define K_   64
#define TP   128     // pixels per block
#define DH   64      // HID chunk
#define NCHUNK (HID_/DH)

// Scratch (device globals: allocation-free rule)
__device__ float        g_mask[(size_t)B_*K_*HW_];   // 128 MB mask buffer
__device__ float        g_wc[B_*3*K_];               // weighted color sums
__device__ float        g_summask[B_*K_];
__device__ unsigned int g_maxmask[B_*K_];

// dynamic smem layout (float offsets)
#define OFF_FEAT 0            // 64*128
#define OFF_H    8192         // 64*128
#define OFF_W1   16384        // 64*64
#define OFF_W2   20480        // 64*64
#define OFF_IMG  24576        // 3*128
#define OFF_LOG  24960        // 128*65 (padded stride 65: conflict-free softmax)
#define OFF_MASK 33280        // 64*128
#define SMEM_FLOATS 41472     // 165,888 bytes

__global__ void __launch_bounds__(256) zero_kernel() {
    int tid = blockIdx.x * blockDim.x + threadIdx.x;
    if (tid < B_*K_) { g_summask[tid] = 0.f; g_maxmask[tid] = 0u; }
    if (tid < B_*3*K_) g_wc[tid] = 0.f;
}

__global__ void __launch_bounds__(256) mask_kernel(
    const float* __restrict__ img, const float* __restrict__ feat,
    const float* __restrict__ w1,  const float* __restrict__ b1,
    const float* __restrict__ w2,  const float* __restrict__ b2)
{
    extern __shared__ float sm[];
    float* sFeat = sm + OFF_FEAT;
    float* sH    = sm + OFF_H;
    float* sW1   = sm + OFF_W1;
    float* sW2   = sm + OFF_W2;
    float* sImg  = sm + OFF_IMG;
    float* sLog  = sm + OFF_LOG;
    float* sMask = sm + OFF_MASK;

    const int tid = threadIdx.x;
    const int b   = blockIdx.x >> 9;          // 512 blocks per batch
    const int p0  = (blockIdx.x & 511) * TP;

    const float* featB = feat + ((size_t)b * CF_) * HW_ + p0;
    const float* imgB  = img  + ((size_t)b * 3)   * HW_ + p0;

    // stage feat tile [c][p] and img tile [c][p]
    for (int idx = tid; idx < CF_*TP; idx += 256) {
        int c = idx >> 7, i = idx & (TP-1);
        sFeat[idx] = featB[(size_t)c * HW_ + i];
    }
    for (int idx = tid; idx < 3*TP; idx += 256) {
        int c = idx >> 7, i = idx & (TP-1);
        sImg[idx] = imgB[(size_t)c * HW_ + i];
    }

    // thread tile mapping: pixels p = tx + 16*i (strided -> conflict-free LDS),
    // channel group dd/k = ty*4 + j
    const int tx = tid & 15;
    const int ty = tid >> 4;

    // persistent logits accumulators [8 pixels][4 k]
    float acc[8][4];
#pragma unroll
    for (int j = 0; j < 4; ++j) {
        float bv = b2[ty*4 + j];
#pragma unroll
        for (int i = 0; i < 8; ++i) acc[i][j] = bv;
    }

    for (int ch = 0; ch < NCHUNK; ++ch) {
        __syncthreads();   // protect sW1/sW2/sH from previous chunk readers
        for (int idx = tid; idx < CF_*DH; idx += 256) {
            int c = idx >> 6, dd = idx & 63;
            sW1[idx] = w1[c * HID_ + ch*DH + dd];
        }
        for (int idx = tid; idx < DH*K_; idx += 256)
            sW2[idx] = w2[ch * DH * K_ + idx];
        __syncthreads();

        // ---- GEMM1 chunk: h[dd][p] = relu(b1 + feat . w1) ----
        float ha[4][8];
#pragma unroll
        for (int j = 0; j < 4; ++j)
#pragma unroll
            for (int i = 0; i < 8; ++i) ha[j][i] = 0.f;

#pragma unroll 8
        for (int c = 0; c < CF_; ++c) {
            float wv[4], fv[8];
#pragma unroll
            for (int j = 0; j < 4; ++j) wv[j] = sW1[c*DH + ty*4 + j];
#pragma unroll
            for (int i = 0; i < 8; ++i) fv[i] = sFeat[c*TP + tx + 16*i];
#pragma unroll
            for (int j = 0; j < 4; ++j)
#pragma unroll
                for (int i = 0; i < 8; ++i)
                    ha[j][i] = fmaf(wv[j], fv[i], ha[j][i]);
        }
#pragma unroll
        for (int j = 0; j < 4; ++j) {
            float bb = b1[ch*DH + ty*4 + j];
#pragma unroll
            for (int i = 0; i < 8; ++i)
                sH[(ty*4+j)*TP + tx + 16*i] = fmaxf(ha[j][i] + bb, 0.f);
        }
        __syncthreads();

        // ---- GEMM2 chunk: logits += h . w2 ----
#pragma unroll 8
        for (int dd = 0; dd < DH; ++dd) {
            float wv[4], hv[8];
#pragma unroll
            for (int j = 0; j < 4; ++j) wv[j] = sW2[dd*K_ + ty*4 + j];
#pragma unroll
            for (int i = 0; i < 8; ++i) hv[i] = sH[dd*TP + tx + 16*i];
#pragma unroll
            for (int i = 0; i < 8; ++i)
#pragma unroll
                for (int j = 0; j < 4; ++j)
                    acc[i][j] = fmaf(hv[i], wv[j], acc[i][j]);
        }
    }
    __syncthreads();

    // scatter logits to [p][k] (stride 65 to avoid bank conflicts)
#pragma unroll
    for (int i = 0; i < 8; ++i)
#pragma unroll
        for (int j = 0; j < 4; ++j)
            sLog[(tx + 16*i)*65 + ty*4 + j] = acc[i][j];
    __syncthreads();

    // softmax over K=64, one thread per pixel
    if (tid < TP) {
        float mx = -1e30f;
#pragma unroll 8
        for (int k = 0; k < K_; ++k) mx = fmaxf(mx, sLog[tid*65 + k]);
        float s = 0.f;
#pragma unroll 8
        for (int k = 0; k < K_; ++k) {
            float e = __expf(sLog[tid*65 + k] - mx);
            sLog[tid*65 + k] = e;
            s += e;
        }
        float inv = 1.0f / s;
#pragma unroll 8
        for (int k = 0; k < K_; ++k)
            sMask[k*TP + tid] = sLog[tid*65 + k] * inv;
    }
    __syncthreads();

    // coalesced mask writeout: layout (b, k, p)
    float* gm = g_mask + ((size_t)b * K_) * HW_ + p0;
    for (int idx = tid; idx < K_*TP; idx += 256) {
        int k = idx >> 7, i = idx & (TP-1);
        gm[(size_t)k * HW_ + i] = sMask[idx];
    }

    // per-(b,k) partial reductions: sum, max, img-weighted sums (3 channels)
    int warp = tid >> 5, lane = tid & 31;
    for (int k = warp; k < K_; k += 8) {
        float s = 0.f, mx = 0.f, a0 = 0.f, a1 = 0.f, a2 = 0.f;
#pragma unroll
        for (int pp = lane; pp < TP; pp += 32) {
            float m = sMask[k*TP + pp];
            s += m;
            mx = fmaxf(mx, m);
            a0 = fmaf(m, sImg[pp],        a0);
            a1 = fmaf(m, sImg[TP + pp],   a1);
            a2 = fmaf(m, sImg[2*TP + pp], a2);
        }
#pragma unroll
        for (int o = 16; o; o >>= 1) {
            s  += __shfl_down_sync(0xffffffffu, s,  o);
            mx  = fmaxf(mx, __shfl_down_sync(0xffffffffu, mx, o));
            a0 += __shfl_down_sync(0xffffffffu, a0, o);
            a1 += __shfl_down_sync(0xffffffffu, a1, o);
            a2 += __shfl_down_sync(0xffffffffu, a2, o);
        }
        if (lane == 0) {
            atomicAdd(&g_summask[b*K_ + k], s);
            atomicMax(&g_maxmask[b*K_ + k], __float_as_uint(mx)); // mask >= 0
            atomicAdd(&g_wc[(b*3 + 0)*K_ + k], a0);
            atomicAdd(&g_wc[(b*3 + 1)*K_ + k], a1);
            atomicAdd(&g_wc[(b*3 + 2)*K_ + k], a2);
        }
    }
}

__global__ void __launch_bounds__(512) finalize_kernel(float* __restrict__ out) {
    __shared__ float sv[512];
    __shared__ float smu[8];
    __shared__ float sstd[8];
    int tid = threadIdx.x;

    float v = g_summask[tid] * (1.0f / (float)HW_);   // mean over hw per (b,k)
    sv[tid] = v;
    __syncthreads();
    if (tid < 8) {
        float mu = 0.f;
        for (int k = 0; k < K_; ++k) mu += sv[tid*K_ + k];
        smu[tid] = mu / (float)K_;
    }
    __syncthreads();
    float d = v - smu[tid >> 6];
    sv[tid] = d * d;
    __syncthreads();
    if (tid < 8) {
        float var = 0.f;
        for (int k = 0; k < K_; ++k) var += sv[tid*K_ + k];
        sstd[tid] = sqrtf(var / 63.0f);               // ddof=1
    }
    __syncthreads();
    sv[tid] = __uint_as_float(g_maxmask[tid]);
    __syncthreads();
    if (tid == 0) {
        float mm = 0.f;
        for (int i = 0; i < B_*K_; ++i) mm += sv[i];
        out[(size_t)B_*3*HW_ + 0] = mm / (float)(B_*K_);      // mean_max
        float sstdm = 0.f;
        for (int bb = 0; bb < B_; ++bb) sstdm += sstd[bb];
        out[(size_t)B_*3*HW_ + 1] = sstdm / (float)B_;        // std_mean
    }
}

__global__ void __launch_bounds__(256) transform_kernel(float* __restrict__ out) {
    const int b = blockIdx.x >> 8;                 // 256 blocks per batch
    const int p = ((blockIdx.x & 255) << 8) + threadIdx.x;
    __shared__ float swc[3*K_];
    if (threadIdx.x < 3*K_)
        swc[threadIdx.x] = g_wc[b*3*K_ + threadIdx.x] * (1.0f / (float)HW_);
    __syncthreads();

    const float* mb = g_mask + ((size_t)b * K_) * HW_ + p;
    float t0 = 0.f, t1 = 0.f, t2 = 0.f;
#pragma unroll
    for (int k = 0; k < K_; ++k) {
        float m = mb[(size_t)k * HW_];
        t0 = fmaf(m, swc[k],        t0);
        t1 = fmaf(m, swc[K_ + k],   t1);
        t2 = fmaf(m, swc[2*K_ + k], t2);
    }
    size_t ob = ((size_t)b * 3) * HW_ + p;
    out[ob]           = t0;
    out[ob + HW_]     = t1;
    out[ob + 2*HW_]   = t2;
}

extern "C" void kernel_launch(void* const* d_in, const int* in_sizes, int n_in,
                              void* d_out, int out_size) {
    const float* img  = (const float*)d_in[0];
    const float* feat = (const float*)d_in[1];
    // d_in[2] = coord_map (unused by reference)
    const float* w1 = (const float*)d_in[3];
    const float* b1 = (const float*)d_in[4];
    const float* w2 = (const float*)d_in[5];
    const float* b2 = (const float*)d_in[6];
    float* out = (float*)d_out;

    cudaFuncSetAttribute(mask_kernel,
                         cudaFuncAttributeMaxDynamicSharedMemorySize,
                         SMEM_FLOATS * (int)sizeof(float));

    zero_kernel<<<6, 256>>>();
    mask_kernel<<<(B_*HW_)/TP, 256, SMEM_FLOATS * sizeof(float)>>>(
        img, feat, w1, b1, w2, b2);
    finalize_kernel<<<1, 512>>>(out);
    transform_kernel<<<(B_*HW_)/256, 256>>>(out);
}

// round 11
// speedup vs baseline: 3.8077x; 3.8077x over previous
#include <cuda_runtime.h>
#include <cuda_bf16.h>
#include <cuda_fp16.h>
#include <math.h>
#include <stdint.h>

#define B_   8
#define CF_  64
#define HW_  65536
#define HID_ 512
#define K_   64
#define TP   128
#define NSUB 8          // HID subchunks of 64
#define THREADS 256

// ---------------- global scratch (allocation-free rule) ----------------
__device__ __half       g_mask[(size_t)B_*K_*HW_];   // fp16 mask (64MB)
__device__ float        g_wc[B_*3*K_];
__device__ float        g_summask[B_*K_];
__device__ unsigned int g_maxmask[B_*K_];
// packed weight tiles per subchunk: [sub][4 tiles][9216B]
// tile order: w1hi, w1lo, w2hi, w2lo. rows padded to 144B (72 bf16).
__device__ __align__(16) unsigned char g_wt[NSUB*4*9216];

// ---------------- SMEM byte layout ----------------
#define FEAT_HI 0            // [128 rows x 72 bf16] (64 used), 144B rows
#define FEAT_LO 18432
#define WBUF    36864        // 2 buffers x 36864 (4 tiles x 9216)
#define B1S     110592       // 512 floats
#define B2S     112640       // 64 floats
#define IMGS    112896       // 3*128 floats
#define SMEM_BYTES 114688
// sMask aliases FEAT region (needs 32KB)
#define ROWB 144

#define LDSM4(R, ADDR) asm volatile( \
    "ldmatrix.sync.aligned.m8n8.x4.shared.b16 {%0,%1,%2,%3}, [%4];" \
    : "=r"((R)[0]), "=r"((R)[1]), "=r"((R)[2]), "=r"((R)[3]) : "r"(ADDR))

#define MMA(D, A, B0, B1) asm volatile( \
    "mma.sync.aligned.m16n8k16.row.col.f32.bf16.bf16.f32 " \
    "{%0,%1,%2,%3}, {%4,%5,%6,%7}, {%8,%9}, {%0,%1,%2,%3};" \
    : "+f"((D)[0]), "+f"((D)[1]), "+f"((D)[2]), "+f"((D)[3]) \
    : "r"((A)[0]), "r"((A)[1]), "r"((A)[2]), "r"((A)[3]), "r"(B0), "r"(B1))

#define CPA16(SM, GP) asm volatile( \
    "cp.async.cg.shared.global [%0], [%1], 16;" :: "r"(SM), "l"(GP) : "memory")
#define CPA_COMMIT() asm volatile("cp.async.commit_group;" ::: "memory")

static __device__ __forceinline__ uint32_t s2u(const void* p){
    uint32_t a;
    asm("{ .reg .u64 t; cvta.to.shared.u64 t, %1; cvt.u32.u64 %0, t; }" : "=r"(a) : "l"(p));
    return a;
}
static __device__ __forceinline__ void split_pair(float x0, float x1,
                                                  uint32_t& hi, uint32_t& lo){
    __nv_bfloat162 h = __floats2bfloat162_rn(x0, x1);
    float2 back = __bfloat1622float2(h);
    __nv_bfloat162 l = __floats2bfloat162_rn(x0 - back.x, x1 - back.y);
    memcpy(&hi, &h, 4); memcpy(&lo, &l, 4);
}

// ---------------- prep: weights -> split/padded tiles ----------------
__global__ void __launch_bounds__(256) prep_kernel(const float* __restrict__ w1,
                                                   const float* __restrict__ w2){
    int t = blockIdx.x * blockDim.x + threadIdx.x;
    if (t < 64*512) {                 // w1[c][d]: B-tile layout [dd][c]
        int c = t >> 9, d = t & 511;
        float x = w1[c*HID_ + d];
        __nv_bfloat16 hi = __float2bfloat16(x);
        __nv_bfloat16 lo = __float2bfloat16(x - __bfloat162float(hi));
        int sub = d >> 6, ddl = d & 63;
        size_t base = (size_t)sub*4*9216;
        *(__nv_bfloat16*)(g_wt + base + 0*9216 + ddl*ROWB + c*2) = hi;
        *(__nv_bfloat16*)(g_wt + base + 1*9216 + ddl*ROWB + c*2) = lo;
    } else if (t < 2*32768) {         // w2[d][k]: B-tile layout [k][dd]
        int u = t - 32768;
        int d = u >> 6, k = u & 63;
        float x = w2[d*K_ + k];
        __nv_bfloat16 hi = __float2bfloat16(x);
        __nv_bfloat16 lo = __float2bfloat16(x - __bfloat162float(hi));
        int sub = d >> 6, ddl = d & 63;
        size_t base = (size_t)sub*4*9216;
        *(__nv_bfloat16*)(g_wt + base + 2*9216 + k*ROWB + ddl*2) = hi;
        *(__nv_bfloat16*)(g_wt + base + 3*9216 + k*ROWB + ddl*2) = lo;
    }
}

__global__ void __launch_bounds__(256) zero_kernel() {
    int tid = blockIdx.x * blockDim.x + threadIdx.x;
    if (tid < B_*K_) { g_summask[tid] = 0.f; g_maxmask[tid] = 0u; }
    if (tid < B_*3*K_) g_wc[tid] = 0.f;
}

// ---------------- fused mask kernel (mma.sync bf16-split) ----------------
__global__ void __launch_bounds__(THREADS)
mask_kernel(const float* __restrict__ img, const float* __restrict__ feat,
            const float* __restrict__ b1, const float* __restrict__ b2)
{
    extern __shared__ char smc[];
    const uint32_t smem_base = s2u(smc);
    const int tid  = threadIdx.x;
    const int wid  = tid >> 5;
    const int lane = tid & 31;

    const int b  = blockIdx.x >> 9;
    const int p0 = (blockIdx.x & 511) * TP;

    float* b1s  = (float*)(smc + B1S);
    float* b2s  = (float*)(smc + B2S);
    float* sImg = (float*)(smc + IMGS);

    // ---- stage biases / img ----
    for (int i = tid; i < HID_; i += THREADS) b1s[i] = b1[i];
    if (tid < K_) b2s[tid] = b2[tid];
    const float* imgB  = img  + ((size_t)b * 3)   * HW_ + p0;
    const float* featB = feat + ((size_t)b * CF_) * HW_ + p0;
    for (int i = tid; i < 3*TP; i += THREADS) {
        int c = i >> 7, p = i & 127;
        sImg[i] = imgB[(size_t)c * HW_ + p];
    }

    // ---- stage feat, split hi/lo (A tiles, 144B rows) ----
    {
        const int p = tid & 127;
        const int cb = (tid >> 7) * 32;
#pragma unroll
        for (int c = cb; c < cb + 32; c += 2) {
            float f0 = featB[(size_t)c     * HW_ + p];
            float f1 = featB[(size_t)(c+1) * HW_ + p];
            uint32_t hi, lo; split_pair(f0, f1, hi, lo);
            *(uint32_t*)(smc + FEAT_HI + p*ROWB + c*2) = hi;
            *(uint32_t*)(smc + FEAT_LO + p*ROWB + c*2) = lo;
        }
    }

    // ---- prefetch weight subchunk 0 ----
    {
        const unsigned char* src = g_wt;
        uint32_t dst = smem_base + WBUF;
        for (int i = tid; i < 2304; i += THREADS)
            CPA16(dst + i*16, src + (size_t)i*16);
        CPA_COMMIT();
    }
    __syncthreads();

    // ---- preload feat A-fragments (reused for all subchunks) ----
    const int m0 = wid * 16;
    uint32_t fa_hi[4][4], fa_lo[4][4];
    {
        uint32_t aHi = smem_base + FEAT_HI + (m0 + (lane & 15))*ROWB + ((lane >> 4) & 1)*16;
        uint32_t aLo = aHi + (FEAT_LO - FEAT_HI);
#pragma unroll
        for (int ks = 0; ks < 4; ++ks) {
            LDSM4(fa_hi[ks], aHi + ks*32);
            LDSM4(fa_lo[ks], aLo + ks*32);
        }
    }

    // per-lane B-tile row offset (within a 9216B tile)
    const uint32_t wrow = (uint32_t)((lane & 7)*ROWB + ((lane >> 3) & 1)*16
                                     + ((lane >> 4) & 1)*9216);
    const int q2 = (lane & 3) * 2;

    float L[8][4];
#pragma unroll
    for (int nt = 0; nt < 8; ++nt)
#pragma unroll
        for (int j = 0; j < 4; ++j) L[nt][j] = 0.f;

    for (int s = 0; s < NSUB; ++s) {
        // prefetch next subchunk into other buffer
        if (s + 1 < NSUB) {
            const unsigned char* src = g_wt + (size_t)(s+1)*36864;
            uint32_t dst = smem_base + WBUF + ((s+1) & 1)*36864;
            for (int i = tid; i < 2304; i += THREADS)
                CPA16(dst + i*16, src + (size_t)i*16);
            CPA_COMMIT();
            asm volatile("cp.async.wait_group 1;" ::: "memory");
        } else {
            asm volatile("cp.async.wait_group 0;" ::: "memory");
        }
        __syncthreads();

        const uint32_t bufb = smem_base + WBUF + (s & 1)*36864;
        const uint32_t w1b = bufb + wrow;            // hi tile 0 / lo tile 1 via wrow bit
        const uint32_t w2b = bufb + 2*9216 + wrow;

        // ---- GEMM1: H[16 x 64] ----
        float Hc[8][4];
#pragma unroll
        for (int nt = 0; nt < 8; ++nt)
#pragma unroll
            for (int j = 0; j < 4; ++j) Hc[nt][j] = 0.f;

#pragma unroll
        for (int ks = 0; ks < 4; ++ks) {
#pragma unroll
            for (int nt = 0; nt < 8; ++nt) {
                uint32_t bf[4];
                LDSM4(bf, w1b + nt*(8*ROWB) + ks*32);   // bf[0,1]=hi frag, bf[2,3]=lo frag
                MMA(Hc[nt], fa_hi[ks], bf[0], bf[1]);
                MMA(Hc[nt], fa_hi[ks], bf[2], bf[3]);
                MMA(Hc[nt], fa_lo[ks], bf[0], bf[1]);
            }
        }

        // ---- bias + relu + split -> A-fragments for GEMM2 (registers only) ----
        uint32_t ha_hi[4][4], ha_lo[4][4];
#pragma unroll
        for (int g = 0; g < 4; ++g) {
#pragma unroll
            for (int h = 0; h < 2; ++h) {
                const int t2 = 2*g + h;
                float2 bv = *(float2*)&b1s[s*64 + t2*8 + q2];
                float x0 = fmaxf(Hc[t2][0] + bv.x, 0.f);
                float x1 = fmaxf(Hc[t2][1] + bv.y, 0.f);
                float x2 = fmaxf(Hc[t2][2] + bv.x, 0.f);
                float x3 = fmaxf(Hc[t2][3] + bv.y, 0.f);
                split_pair(x0, x1, ha_hi[g][2*h+0], ha_lo[g][2*h+0]);
                split_pair(x2, x3, ha_hi[g][2*h+1], ha_lo[g][2*h+1]);
            }
        }

        // ---- GEMM2: logits += H @ w2sub ----
#pragma unroll
        for (int ks = 0; ks < 4; ++ks) {
#pragma unroll
            for (int nt = 0; nt < 8; ++nt) {
                uint32_t bf[4];
                LDSM4(bf, w2b + nt*(8*ROWB) + ks*32);
                MMA(L[nt], ha_hi[ks], bf[0], bf[1]);
                MMA(L[nt], ha_hi[ks], bf[2], bf[3]);
                MMA(L[nt], ha_lo[ks], bf[0], bf[1]);
            }
        }
        __syncthreads();   // retire reads of buf[s&1] before it is overwritten
    }

    // ---- epilogue: +b2, softmax over 64 k (4-lane row groups) ----
#pragma unroll
    for (int nt = 0; nt < 8; ++nt) {
        float2 bv = *(float2*)&b2s[nt*8 + q2];
        L[nt][0] += bv.x; L[nt][1] += bv.y;
        L[nt][2] += bv.x; L[nt][3] += bv.y;
    }
    float mx0 = -1e30f, mx1 = -1e30f;
#pragma unroll
    for (int nt = 0; nt < 8; ++nt) {
        mx0 = fmaxf(mx0, fmaxf(L[nt][0], L[nt][1]));
        mx1 = fmaxf(mx1, fmaxf(L[nt][2], L[nt][3]));
    }
    mx0 = fmaxf(mx0, __shfl_xor_sync(0xffffffffu, mx0, 1));
    mx0 = fmaxf(mx0, __shfl_xor_sync(0xffffffffu, mx0, 2));
    mx1 = fmaxf(mx1, __shfl_xor_sync(0xffffffffu, mx1, 1));
    mx1 = fmaxf(mx1, __shfl_xor_sync(0xffffffffu, mx1, 2));
    float s0 = 0.f, s1 = 0.f;
#pragma unroll
    for (int nt = 0; nt < 8; ++nt) {
        L[nt][0] = __expf(L[nt][0] - mx0); s0 += L[nt][0];
        L[nt][1] = __expf(L[nt][1] - mx0); s0 += L[nt][1];
        L[nt][2] = __expf(L[nt][2] - mx1); s1 += L[nt][2];
        L[nt][3] = __expf(L[nt][3] - mx1); s1 += L[nt][3];
    }
    s0 += __shfl_xor_sync(0xffffffffu, s0, 1);
    s0 += __shfl_xor_sync(0xffffffffu, s0, 2);
    s1 += __shfl_xor_sync(0xffffffffu, s1, 1);
    s1 += __shfl_xor_sync(0xffffffffu, s1, 2);
    const float inv0 = 1.0f / s0, inv1 = 1.0f / s1;

    // ---- mask to SMEM [k][p] (aliases feat region; feat now lives in regs) ----
    float* sMask = (float*)smc;
    __syncthreads();
    {
        const int pr = m0 + (lane >> 2);
#pragma unroll
        for (int nt = 0; nt < 8; ++nt) {
#pragma unroll
            for (int j = 0; j < 2; ++j) {
                int k = nt*8 + q2 + j;
                sMask[k*TP + pr]     = L[nt][j]     * inv0;
                sMask[k*TP + pr + 8] = L[nt][2 + j] * inv1;
            }
        }
    }
    __syncthreads();

    // ---- fp16 mask writeout (b, k, p), half2 packed ----
    __half* gm = g_mask + ((size_t)b * K_) * HW_ + p0;
    for (int idx = tid; idx < K_*64; idx += THREADS) {
        int k = idx >> 6, pi = (idx & 63) * 2;
        __half2 v = __floats2half2_rn(sMask[k*TP + pi], sMask[k*TP + pi + 1]);
        *(__half2*)(gm + (size_t)k * HW_ + pi) = v;
    }

    // ---- per-(b,k) partial reductions ----
    for (int k = wid; k < K_; k += 8) {
        float ss = 0.f, mm = 0.f, a0 = 0.f, a1 = 0.f, a2 = 0.f;
#pragma unroll
        for (int pp = lane; pp < TP; pp += 32) {
            float mval = sMask[k*TP + pp];
            ss += mval;
            mm = fmaxf(mm, mval);
            a0 = fmaf(mval, sImg[pp],        a0);
            a1 = fmaf(mval, sImg[TP + pp],   a1);
            a2 = fmaf(mval, sImg[2*TP + pp], a2);
        }
#pragma unroll
        for (int o = 16; o; o >>= 1) {
            ss += __shfl_down_sync(0xffffffffu, ss, o);
            mm  = fmaxf(mm, __shfl_down_sync(0xffffffffu, mm, o));
            a0 += __shfl_down_sync(0xffffffffu, a0, o);
            a1 += __shfl_down_sync(0xffffffffu, a1, o);
            a2 += __shfl_down_sync(0xffffffffu, a2, o);
        }
        if (lane == 0) {
            atomicAdd(&g_summask[b*K_ + k], ss);
            atomicMax(&g_maxmask[b*K_ + k], __float_as_uint(mm));
            atomicAdd(&g_wc[(b*3 + 0)*K_ + k], a0);
            atomicAdd(&g_wc[(b*3 + 1)*K_ + k], a1);
            atomicAdd(&g_wc[(b*3 + 2)*K_ + k], a2);
        }
    }
}

__global__ void __launch_bounds__(512) finalize_kernel(float* __restrict__ out) {
    __shared__ float sv[512];
    __shared__ float smu[8];
    __shared__ float sstd[8];
    int tid = threadIdx.x;

    float v = g_summask[tid] * (1.0f / (float)HW_);
    sv[tid] = v;
    __syncthreads();
    if (tid < 8) {
        float mu = 0.f;
        for (int k = 0; k < K_; ++k) mu += sv[tid*K_ + k];
        smu[tid] = mu / (float)K_;
    }
    __syncthreads();
    float d = v - smu[tid >> 6];
    sv[tid] = d * d;
    __syncthreads();
    if (tid < 8) {
        float var = 0.f;
        for (int k = 0; k < K_; ++k) var += sv[tid*K_ + k];
        sstd[tid] = sqrtf(var / 63.0f);
    }
    __syncthreads();
    sv[tid] = __uint_as_float(g_maxmask[tid]);
    __syncthreads();
    if (tid == 0) {
        float mm = 0.f;
        for (int i = 0; i < B_*K_; ++i) mm += sv[i];
        out[(size_t)B_*3*HW_ + 0] = mm / (float)(B_*K_);
        float sstdm = 0.f;
        for (int bb = 0; bb < B_; ++bb) sstdm += sstd[bb];
        out[(size_t)B_*3*HW_ + 1] = sstdm / (float)B_;
    }
}

__global__ void __launch_bounds__(256) transform_kernel(float* __restrict__ out) {
    const int b = blockIdx.x >> 8;
    const int p = ((blockIdx.x & 255) << 8) + threadIdx.x;
    __shared__ float swc[3*K_];
    if (threadIdx.x < 3*K_)
        swc[threadIdx.x] = g_wc[b*3*K_ + threadIdx.x] * (1.0f / (float)HW_);
    __syncthreads();

    const __half* mb = g_mask + ((size_t)b * K_) * HW_ + p;
    float t0 = 0.f, t1 = 0.f, t2 = 0.f;
#pragma unroll
    for (int k = 0; k < K_; ++k) {
        float m = __half2float(mb[(size_t)k * HW_]);
        t0 = fmaf(m, swc[k],        t0);
        t1 = fmaf(m, swc[K_ + k],   t1);
        t2 = fmaf(m, swc[2*K_ + k], t2);
    }
    size_t ob = ((size_t)b * 3) * HW_ + p;
    out[ob]         = t0;
    out[ob + HW_]   = t1;
    out[ob + 2*HW_] = t2;
}

extern "C" void kernel_launch(void* const* d_in, const int* in_sizes, int n_in,
                              void* d_out, int out_size) {
    const float* img  = (const float*)d_in[0];
    const float* feat = (const float*)d_in[1];
    // d_in[2] = coord_map (unused by reference)
    const float* w1 = (const float*)d_in[3];
    const float* b1 = (const float*)d_in[4];
    const float* w2 = (const float*)d_in[5];
    const float* b2 = (const float*)d_in[6];
    float* out = (float*)d_out;

    cudaFuncSetAttribute(mask_kernel,
                         cudaFuncAttributeMaxDynamicSharedMemorySize, SMEM_BYTES);

    prep_kernel<<<256, 256>>>(w1, w2);
    zero_kernel<<<6, 256>>>();
    mask_kernel<<<(B_*HW_)/TP, THREADS, SMEM_BYTES>>>(img, feat, b1, b2);
    finalize_kernel<<<1, 512>>>(out);
    transform_kernel<<<(B_*HW_)/256, 256>>>(out);
}

// round 12
// speedup vs baseline: 3.9373x; 1.0340x over previous
#include <cuda_runtime.h>
#include <cuda_bf16.h>
#include <cuda_fp16.h>
#include <math.h>
#include <stdint.h>

#define B_   8
#define CF_  64
#define HW_  65536
#define HID_ 512
#define K_   64
#define TP   128
#define NSUB 8          // HID subchunks of 64
#define THREADS 256

// ---------------- global scratch (allocation-free rule) ----------------
__device__ __half       g_mask[(size_t)B_*K_*HW_];   // fp16 mask (64MB)
__device__ float        g_wc[B_*3*K_];
__device__ float        g_summask[B_*K_];
__device__ unsigned int g_maxmask[B_*K_];
// packed weight tiles per subchunk: [sub][4 tiles][9216B]
// tile order: w1hi, w1lo, w2hi, w2lo. rows padded to 144B (72 bf16).
__device__ __align__(16) unsigned char g_wt[NSUB*4*9216];

// ---------------- SMEM byte layout (region A/B aliasing) ----------------
// Region A [0, 36864): feat hi/lo during staging; weight buffer for ODD subchunks.
// Region B [36864, 73728): weight buffer for EVEN subchunks; sMask after mainloop.
#define FEAT_HI 0            // [128 rows x 72 bf16], 144B rows
#define FEAT_LO 18432
#define REG_A   0
#define REG_B   36864
#define SMASK_OFF 36864      // 32KB, in region B
#define B1S     73728        // 512 floats
#define B2S     75776        // 64 floats
#define IMGS    76032        // 3*128 floats
#define SMEM_BYTES 77824
#define ROWB 144

#define LDSM4(R, ADDR) asm volatile( \
    "ldmatrix.sync.aligned.m8n8.x4.shared.b16 {%0,%1,%2,%3}, [%4];" \
    : "=r"((R)[0]), "=r"((R)[1]), "=r"((R)[2]), "=r"((R)[3]) : "r"(ADDR))

#define MMA(D, A, B0, B1) asm volatile( \
    "mma.sync.aligned.m16n8k16.row.col.f32.bf16.bf16.f32 " \
    "{%0,%1,%2,%3}, {%4,%5,%6,%7}, {%8,%9}, {%0,%1,%2,%3};" \
    : "+f"((D)[0]), "+f"((D)[1]), "+f"((D)[2]), "+f"((D)[3]) \
    : "r"((A)[0]), "r"((A)[1]), "r"((A)[2]), "r"((A)[3]), "r"(B0), "r"(B1))

#define CPA16(SM, GP) asm volatile( \
    "cp.async.cg.shared.global [%0], [%1], 16;" :: "r"(SM), "l"(GP) : "memory")
#define CPA_COMMIT() asm volatile("cp.async.commit_group;" ::: "memory")

static __device__ __forceinline__ uint32_t s2u(const void* p){
    uint32_t a;
    asm("{ .reg .u64 t; cvta.to.shared.u64 t, %1; cvt.u32.u64 %0, t; }" : "=r"(a) : "l"(p));
    return a;
}
static __device__ __forceinline__ void split_pair(float x0, float x1,
                                                  uint32_t& hi, uint32_t& lo){
    __nv_bfloat162 h = __floats2bfloat162_rn(x0, x1);
    float2 back = __bfloat1622float2(h);
    __nv_bfloat162 l = __floats2bfloat162_rn(x0 - back.x, x1 - back.y);
    memcpy(&hi, &h, 4); memcpy(&lo, &l, 4);
}

// ---------------- prep: weights -> split/padded tiles ----------------
__global__ void __launch_bounds__(256) prep_kernel(const float* __restrict__ w1,
                                                   const float* __restrict__ w2){
    int t = blockIdx.x * blockDim.x + threadIdx.x;
    if (t < 64*512) {                 // w1[c][d]: B-tile layout [dd][c]
        int c = t >> 9, d = t & 511;
        float x = w1[c*HID_ + d];
        __nv_bfloat16 hi = __float2bfloat16(x);
        __nv_bfloat16 lo = __float2bfloat16(x - __bfloat162float(hi));
        int sub = d >> 6, ddl = d & 63;
        size_t base = (size_t)sub*4*9216;
        *(__nv_bfloat16*)(g_wt + base + 0*9216 + ddl*ROWB + c*2) = hi;
        *(__nv_bfloat16*)(g_wt + base + 1*9216 + ddl*ROWB + c*2) = lo;
    } else if (t < 2*32768) {         // w2[d][k]: B-tile layout [k][dd]
        int u = t - 32768;
        int d = u >> 6, k = u & 63;
        float x = w2[d*K_ + k];
        __nv_bfloat16 hi = __float2bfloat16(x);
        __nv_bfloat16 lo = __float2bfloat16(x - __bfloat162float(hi));
        int sub = d >> 6, ddl = d & 63;
        size_t base = (size_t)sub*4*9216;
        *(__nv_bfloat16*)(g_wt + base + 2*9216 + k*ROWB + ddl*2) = hi;
        *(__nv_bfloat16*)(g_wt + base + 3*9216 + k*ROWB + ddl*2) = lo;
    }
}

__global__ void __launch_bounds__(256) zero_kernel() {
    int tid = blockIdx.x * blockDim.x + threadIdx.x;
    if (tid < B_*K_) { g_summask[tid] = 0.f; g_maxmask[tid] = 0u; }
    if (tid < B_*3*K_) g_wc[tid] = 0.f;
}

// ---------------- fused mask kernel (mma.sync bf16-split) ----------------
__global__ void __launch_bounds__(THREADS, 2)
mask_kernel(const float* __restrict__ img, const float* __restrict__ feat,
            const float* __restrict__ b1, const float* __restrict__ b2)
{
    extern __shared__ char smc[];
    const uint32_t smem_base = s2u(smc);
    const int tid  = threadIdx.x;
    const int wid  = tid >> 5;
    const int lane = tid & 31;

    const int b  = blockIdx.x >> 9;
    const int p0 = (blockIdx.x & 511) * TP;

    float* b1s  = (float*)(smc + B1S);
    float* b2s  = (float*)(smc + B2S);
    float* sImg = (float*)(smc + IMGS);

    // ---- prefetch weight subchunk 0 into region B FIRST (overlaps feat staging) ----
    {
        const unsigned char* src = g_wt;
        uint32_t dst = smem_base + REG_B;
        for (int i = tid; i < 2304; i += THREADS)
            CPA16(dst + i*16, src + (size_t)i*16);
        CPA_COMMIT();
    }

    // ---- stage biases / img ----
    for (int i = tid; i < HID_; i += THREADS) b1s[i] = b1[i];
    if (tid < K_) b2s[tid] = b2[tid];
    const float* imgB  = img  + ((size_t)b * 3)   * HW_ + p0;
    const float* featB = feat + ((size_t)b * CF_) * HW_ + p0;
    for (int i = tid; i < 3*TP; i += THREADS) {
        int c = i >> 7, p = i & 127;
        sImg[i] = imgB[(size_t)c * HW_ + p];
    }

    // ---- stage feat, split hi/lo into region A (144B rows) ----
    {
        const int p = tid & 127;
        const int cb = (tid >> 7) * 32;
#pragma unroll
        for (int c = cb; c < cb + 32; c += 2) {
            float f0 = featB[(size_t)c     * HW_ + p];
            float f1 = featB[(size_t)(c+1) * HW_ + p];
            uint32_t hi, lo; split_pair(f0, f1, hi, lo);
            *(uint32_t*)(smc + FEAT_HI + p*ROWB + c*2) = hi;
            *(uint32_t*)(smc + FEAT_LO + p*ROWB + c*2) = lo;
        }
    }
    __syncthreads();

    // ---- preload feat A-fragments (reused for all subchunks) ----
    const int m0 = wid * 16;
    uint32_t fa_hi[4][4], fa_lo[4][4];
    {
        uint32_t aHi = smem_base + FEAT_HI + (m0 + (lane & 15))*ROWB + ((lane >> 4) & 1)*16;
        uint32_t aLo = aHi + (FEAT_LO - FEAT_HI);
#pragma unroll
        for (int ks = 0; ks < 4; ++ks) {
            LDSM4(fa_hi[ks], aHi + ks*32);
            LDSM4(fa_lo[ks], aLo + ks*32);
        }
    }
    __syncthreads();   // region A (feat) reads retired before subchunk-1 prefetch overwrites it

    // per-lane B-tile row offset (within a 9216B tile)
    const uint32_t wrow = (uint32_t)((lane & 7)*ROWB + ((lane >> 3) & 1)*16
                                     + ((lane >> 4) & 1)*9216);
    const int q2 = (lane & 3) * 2;

    float L[8][4];
#pragma unroll
    for (int nt = 0; nt < 8; ++nt)
#pragma unroll
        for (int j = 0; j < 4; ++j) L[nt][j] = 0.f;

    for (int s = 0; s < NSUB; ++s) {
        // prefetch next subchunk into the other region (odd->A, even->B)
        if (s + 1 < NSUB) {
            const unsigned char* src = g_wt + (size_t)(s+1)*36864;
            uint32_t dst = smem_base + (((s+1) & 1) ? REG_A : REG_B);
            for (int i = tid; i < 2304; i += THREADS)
                CPA16(dst + i*16, src + (size_t)i*16);
            CPA_COMMIT();
            asm volatile("cp.async.wait_group 1;" ::: "memory");
        } else {
            asm volatile("cp.async.wait_group 0;" ::: "memory");
        }
        __syncthreads();

        const uint32_t bufb = smem_base + ((s & 1) ? REG_A : REG_B);
        const uint32_t w1b = bufb + wrow;            // hi tile 0 / lo tile 1 via wrow bit
        const uint32_t w2b = bufb + 2*9216 + wrow;

        // ---- GEMM1: H[16 x 64] ----
        float Hc[8][4];
#pragma unroll
        for (int nt = 0; nt < 8; ++nt)
#pragma unroll
            for (int j = 0; j < 4; ++j) Hc[nt][j] = 0.f;

#pragma unroll
        for (int ks = 0; ks < 4; ++ks) {
#pragma unroll
            for (int nt = 0; nt < 8; ++nt) {
                uint32_t bf[4];
                LDSM4(bf, w1b + nt*(8*ROWB) + ks*32);   // bf[0,1]=hi frag, bf[2,3]=lo frag
                MMA(Hc[nt], fa_hi[ks], bf[0], bf[1]);
                MMA(Hc[nt], fa_hi[ks], bf[2], bf[3]);
                MMA(Hc[nt], fa_lo[ks], bf[0], bf[1]);
            }
        }

        // ---- GEMM2 interleaved: per k-step g, build H A-frag in regs then MMA ----
#pragma unroll
        for (int g = 0; g < 4; ++g) {
            uint32_t ha_hi[4], ha_lo[4];
#pragma unroll
            for (int h = 0; h < 2; ++h) {
                const int t2 = 2*g + h;
                float2 bv = *(float2*)&b1s[s*64 + t2*8 + q2];
                float x0 = fmaxf(Hc[t2][0] + bv.x, 0.f);
                float x1 = fmaxf(Hc[t2][1] + bv.y, 0.f);
                float x2 = fmaxf(Hc[t2][2] + bv.x, 0.f);
                float x3 = fmaxf(Hc[t2][3] + bv.y, 0.f);
                split_pair(x0, x1, ha_hi[2*h+0], ha_lo[2*h+0]);
                split_pair(x2, x3, ha_hi[2*h+1], ha_lo[2*h+1]);
            }
#pragma unroll
            for (int nt = 0; nt < 8; ++nt) {
                uint32_t bf[4];
                LDSM4(bf, w2b + nt*(8*ROWB) + g*32);
                MMA(L[nt], ha_hi, bf[0], bf[1]);
                MMA(L[nt], ha_hi, bf[2], bf[3]);
                MMA(L[nt], ha_lo, bf[0], bf[1]);
            }
        }
        __syncthreads();   // retire reads of this buffer before it is overwritten
    }

    // ---- epilogue: +b2, softmax over 64 k (4-lane row groups) ----
#pragma unroll
    for (int nt = 0; nt < 8; ++nt) {
        float2 bv = *(float2*)&b2s[nt*8 + q2];
        L[nt][0] += bv.x; L[nt][1] += bv.y;
        L[nt][2] += bv.x; L[nt][3] += bv.y;
    }
    float mx0 = -1e30f, mx1 = -1e30f;
#pragma unroll
    for (int nt = 0; nt < 8; ++nt) {
        mx0 = fmaxf(mx0, fmaxf(L[nt][0], L[nt][1]));
        mx1 = fmaxf(mx1, fmaxf(L[nt][2], L[nt][3]));
    }
    mx0 = fmaxf(mx0, __shfl_xor_sync(0xffffffffu, mx0, 1));
    mx0 = fmaxf(mx0, __shfl_xor_sync(0xffffffffu, mx0, 2));
    mx1 = fmaxf(mx1, __shfl_xor_sync(0xffffffffu, mx1, 1));
    mx1 = fmaxf(mx1, __shfl_xor_sync(0xffffffffu, mx1, 2));
    float s0 = 0.f, s1 = 0.f;
#pragma unroll
    for (int nt = 0; nt < 8; ++nt) {
        L[nt][0] = __expf(L[nt][0] - mx0); s0 += L[nt][0];
        L[nt][1] = __expf(L[nt][1] - mx0); s0 += L[nt][1];
        L[nt][2] = __expf(L[nt][2] - mx1); s1 += L[nt][2];
        L[nt][3] = __expf(L[nt][3] - mx1); s1 += L[nt][3];
    }
    s0 += __shfl_xor_sync(0xffffffffu, s0, 1);
    s0 += __shfl_xor_sync(0xffffffffu, s0, 2);
    s1 += __shfl_xor_sync(0xffffffffu, s1, 1);
    s1 += __shfl_xor_sync(0xffffffffu, s1, 2);
    const float inv0 = 1.0f / s0, inv1 = 1.0f / s1;

    // ---- mask to SMEM [k][p] in region B (weights consumed) ----
    float* sMask = (float*)(smc + SMASK_OFF);
    __syncthreads();
    {
        const int pr = m0 + (lane >> 2);
#pragma unroll
        for (int nt = 0; nt < 8; ++nt) {
#pragma unroll
            for (int j = 0; j < 2; ++j) {
                int k = nt*8 + q2 + j;
                sMask[k*TP + pr]     = L[nt][j]     * inv0;
                sMask[k*TP + pr + 8] = L[nt][2 + j] * inv1;
            }
        }
    }
    __syncthreads();

    // ---- fp16 mask writeout (b, k, p), half2 packed ----
    __half* gm = g_mask + ((size_t)b * K_) * HW_ + p0;
    for (int idx = tid; idx < K_*64; idx += THREADS) {
        int k = idx >> 6, pi = (idx & 63) * 2;
        __half2 v = __floats2half2_rn(sMask[k*TP + pi], sMask[k*TP + pi + 1]);
        *(__half2*)(gm + (size_t)k * HW_ + pi) = v;
    }

    // ---- per-(b,k) partial reductions ----
    for (int k = wid; k < K_; k += 8) {
        float ss = 0.f, mm = 0.f, a0 = 0.f, a1 = 0.f, a2 = 0.f;
#pragma unroll
        for (int pp = lane; pp < TP; pp += 32) {
            float mval = sMask[k*TP + pp];
            ss += mval;
            mm = fmaxf(mm, mval);
            a0 = fmaf(mval, sImg[pp],        a0);
            a1 = fmaf(mval, sImg[TP + pp],   a1);
            a2 = fmaf(mval, sImg[2*TP + pp], a2);
        }
#pragma unroll
        for (int o = 16; o; o >>= 1) {
            ss += __shfl_down_sync(0xffffffffu, ss, o);
            mm  = fmaxf(mm, __shfl_down_sync(0xffffffffu, mm, o));
            a0 += __shfl_down_sync(0xffffffffu, a0, o);
            a1 += __shfl_down_sync(0xffffffffu, a1, o);
            a2 += __shfl_down_sync(0xffffffffu, a2, o);
        }
        if (lane == 0) {
            atomicAdd(&g_summask[b*K_ + k], ss);
            atomicMax(&g_maxmask[b*K_ + k], __float_as_uint(mm));
            atomicAdd(&g_wc[(b*3 + 0)*K_ + k], a0);
            atomicAdd(&g_wc[(b*3 + 1)*K_ + k], a1);
            atomicAdd(&g_wc[(b*3 + 2)*K_ + k], a2);
        }
    }
}

__global__ void __launch_bounds__(512) finalize_kernel(float* __restrict__ out) {
    __shared__ float sv[512];
    __shared__ float smu[8];
    __shared__ float sstd[8];
    int tid = threadIdx.x;

    float v = g_summask[tid] * (1.0f / (float)HW_);
    sv[tid] = v;
    __syncthreads();
    if (tid < 8) {
        float mu = 0.f;
        for (int k = 0; k < K_; ++k) mu += sv[tid*K_ + k];
        smu[tid] = mu / (float)K_;
    }
    __syncthreads();
    float d = v - smu[tid >> 6];
    sv[tid] = d * d;
    __syncthreads();
    if (tid < 8) {
        float var = 0.f;
        for (int k = 0; k < K_; ++k) var += sv[tid*K_ + k];
        sstd[tid] = sqrtf(var / 63.0f);
    }
    __syncthreads();
    sv[tid] = __uint_as_float(g_maxmask[tid]);
    __syncthreads();
    if (tid == 0) {
        float mm = 0.f;
        for (int i = 0; i < B_*K_; ++i) mm += sv[i];
        out[(size_t)B_*3*HW_ + 0] = mm / (float)(B_*K_);
        float sstdm = 0.f;
        for (int bb = 0; bb < B_; ++bb) sstdm += sstd[bb];
        out[(size_t)B_*3*HW_ + 1] = sstdm / (float)B_;
    }
}

__global__ void __launch_bounds__(256) transform_kernel(float* __restrict__ out) {
    const int b = blockIdx.x >> 8;
    const int p = ((blockIdx.x & 255) << 8) + threadIdx.x;
    __shared__ float swc[3*K_];
    if (threadIdx.x < 3*K_)
        swc[threadIdx.x] = g_wc[b*3*K_ + threadIdx.x] * (1.0f / (float)HW_);
    __syncthreads();

    const __half* mb = g_mask + ((size_t)b * K_) * HW_ + p;
    float t0 = 0.f, t1 = 0.f, t2 = 0.f;
#pragma unroll
    for (int k = 0; k < K_; ++k) {
        float m = __half2float(mb[(size_t)k * HW_]);
        t0 = fmaf(m, swc[k],        t0);
        t1 = fmaf(m, swc[K_ + k],   t1);
        t2 = fmaf(m, swc[2*K_ + k], t2);
    }
    size_t ob = ((size_t)b * 3) * HW_ + p;
    out[ob]         = t0;
    out[ob + HW_]   = t1;
    out[ob + 2*HW_] = t2;
}

extern "C" void kernel_launch(void* const* d_in, const int* in_sizes, int n_in,
                              void* d_out, int out_size) {
    const float* img  = (const float*)d_in[0];
    const float* feat = (const float*)d_in[1];
    // d_in[2] = coord_map (unused by reference)
    const float* w1 = (const float*)d_in[3];
    const float* b1 = (const float*)d_in[4];
    const float* w2 = (const float*)d_in[5];
    const float* b2 = (const float*)d_in[6];
    float* out = (float*)d_out;

    cudaFuncSetAttribute(mask_kernel,
                         cudaFuncAttributeMaxDynamicSharedMemorySize, SMEM_BYTES);

    prep_kernel<<<256, 256>>>(w1, w2);
    zero_kernel<<<6, 256>>>();
    mask_kernel<<<(B_*HW_)/TP, THREADS, SMEM_BYTES>>>(img, feat, b1, b2);
    finalize_kernel<<<1, 512>>>(out);
    transform_kernel<<<(B_*HW_)/256, 256>>>(out);
}

// round 17
// speedup vs baseline: 4.8897x; 1.2419x over previous
#include <cuda_runtime.h>
#include <cuda_bf16.h>
#include <cuda_fp16.h>
#include <math.h>
#include <stdint.h>

#define B_   8
#define CF_  64
#define HW_  65536
#define HID_ 512
#define K_   64
#define TP   128
#define NSUB 8          // HID subchunks of 64
#define THREADS 256

// ---------------- global scratch (allocation-free rule) ----------------
__device__ __half       g_mask[(size_t)B_*K_*HW_];   // fp16 mask (64MB)
__device__ float        g_wc[B_*3*K_];
__device__ float        g_summask[B_*K_];
__device__ unsigned int g_maxmask[B_*K_];
// packed fp16 weight tiles per subchunk: [sub][4 tiles][9216B]
// tile order: w1hi, w1lo, w2hi, w2lo. rows padded to 144B (72 fp16).
__device__ __align__(16) unsigned char g_wt[NSUB*4*9216];

// ---------------- SMEM byte layout (region A/B aliasing) ----------------
// Region A [0, 36864): feat fp16 tile during staging; weight buffer for ODD subchunks.
// Region B [36864, 73728): weight buffer for EVEN subchunks; sMask after mainloop.
#define FEAT_OFF 0           // [128 rows x 72 fp16], 144B rows (18KB used)
#define REG_A   0
#define REG_B   36864
#define SMASK_OFF 36864      // 32KB, in region B
#define B1S     73728        // 512 floats
#define B2S     75776        // 64 floats
#define IMGS    76032        // 3*128 floats
#define SMEM_BYTES 77824
#define ROWB 144

#define LDSM4(R, ADDR) asm volatile( \
    "ldmatrix.sync.aligned.m8n8.x4.shared.b16 {%0,%1,%2,%3}, [%4];" \
    : "=r"((R)[0]), "=r"((R)[1]), "=r"((R)[2]), "=r"((R)[3]) : "r"(ADDR))

#define MMA(D, A, B0, B1) asm volatile( \
    "mma.sync.aligned.m16n8k16.row.col.f32.f16.f16.f32 " \
    "{%0,%1,%2,%3}, {%4,%5,%6,%7}, {%8,%9}, {%0,%1,%2,%3};" \
    : "+f"((D)[0]), "+f"((D)[1]), "+f"((D)[2]), "+f"((D)[3]) \
    : "r"((A)[0]), "r"((A)[1]), "r"((A)[2]), "r"((A)[3]), "r"(B0), "r"(B1))

#define CPA16(SM, GP) asm volatile( \
    "cp.async.cg.shared.global [%0], [%1], 16;" :: "r"(SM), "l"(GP) : "memory")
#define CPA_COMMIT() asm volatile("cp.async.commit_group;" ::: "memory")

static __device__ __forceinline__ uint32_t s2u(const void* p){
    uint32_t a;
    asm("{ .reg .u64 t; cvta.to.shared.u64 t, %1; cvt.u32.u64 %0, t; }" : "=r"(a) : "l"(p));
    return a;
}
static __device__ __forceinline__ uint32_t pack2h(float x0, float x1){
    __half2 h = __floats2half2_rn(x0, x1);
    uint32_t u; memcpy(&u, &h, 4); return u;
}

// ---------------- prep: weights -> fp16 hi/lo padded tiles ----------------
__global__ void __launch_bounds__(256) prep_kernel(const float* __restrict__ w1,
                                                   const float* __restrict__ w2){
    int t = blockIdx.x * blockDim.x + threadIdx.x;
    if (t < 64*512) {                 // w1[c][d]: B-tile layout [dd][c]
        int c = t >> 9, d = t & 511;
        float x = w1[c*HID_ + d];
        __half hi = __float2half_rn(x);
        __half lo = __float2half_rn(x - __half2float(hi));
        int sub = d >> 6, ddl = d & 63;
        size_t base = (size_t)sub*4*9216;
        *(__half*)(g_wt + base + 0*9216 + ddl*ROWB + c*2) = hi;
        *(__half*)(g_wt + base + 1*9216 + ddl*ROWB + c*2) = lo;
    } else if (t < 2*32768) {         // w2[d][k]: B-tile layout [k][dd]
        int u = t - 32768;
        int d = u >> 6, k = u & 63;
        float x = w2[d*K_ + k];
        __half hi = __float2half_rn(x);
        __half lo = __float2half_rn(x - __half2float(hi));
        int sub = d >> 6, ddl = d & 63;
        size_t base = (size_t)sub*4*9216;
        *(__half*)(g_wt + base + 2*9216 + k*ROWB + ddl*2) = hi;
        *(__half*)(g_wt + base + 3*9216 + k*ROWB + ddl*2) = lo;
    }
}

__global__ void __launch_bounds__(256) zero_kernel() {
    int tid = blockIdx.x * blockDim.x + threadIdx.x;
    if (tid < B_*K_) { g_summask[tid] = 0.f; g_maxmask[tid] = 0u; }
    if (tid < B_*3*K_) g_wc[tid] = 0.f;
}

// ---------------- fused mask kernel (mma.sync fp16 2-term) ----------------
__global__ void __launch_bounds__(THREADS, 2)
mask_kernel(const float* __restrict__ img, const float* __restrict__ feat,
            const float* __restrict__ b1, const float* __restrict__ b2)
{
    extern __shared__ char smc[];
    const uint32_t smem_base = s2u(smc);
    const int tid  = threadIdx.x;
    const int wid  = tid >> 5;
    const int lane = tid & 31;

    const int b  = blockIdx.x >> 9;
    const int p0 = (blockIdx.x & 511) * TP;

    float* b1s  = (float*)(smc + B1S);
    float* b2s  = (float*)(smc + B2S);
    float* sImg = (float*)(smc + IMGS);

    // ---- prefetch weight subchunk 0 into region B FIRST (overlaps feat staging) ----
    {
        const unsigned char* src = g_wt;
        uint32_t dst = smem_base + REG_B;
        for (int i = tid; i < 2304; i += THREADS)
            CPA16(dst + i*16, src + (size_t)i*16);
        CPA_COMMIT();
    }

    // ---- stage biases / img ----
    for (int i = tid; i < HID_; i += THREADS) b1s[i] = b1[i];
    if (tid < K_) b2s[tid] = b2[tid];
    const float* imgB  = img  + ((size_t)b * 3)   * HW_ + p0;
    const float* featB = feat + ((size_t)b * CF_) * HW_ + p0;
    for (int i = tid; i < 3*TP; i += THREADS) {
        int c = i >> 7, p = i & 127;
        sImg[i] = imgB[(size_t)c * HW_ + p];
    }

    // ---- stage feat as single fp16 tile in region A (144B rows) ----
    {
        const int p = tid & 127;
        const int cb = (tid >> 7) * 32;
#pragma unroll
        for (int c = cb; c < cb + 32; c += 2) {
            float f0 = featB[(size_t)c     * HW_ + p];
            float f1 = featB[(size_t)(c+1) * HW_ + p];
            *(uint32_t*)(smc + FEAT_OFF + p*ROWB + c*2) = pack2h(f0, f1);
        }
    }
    __syncthreads();

    // ---- preload feat A-fragments (reused for all subchunks) ----
    const int m0 = wid * 16;
    uint32_t fa[4][4];
    {
        uint32_t aAd = smem_base + FEAT_OFF + (m0 + (lane & 15))*ROWB + ((lane >> 4) & 1)*16;
#pragma unroll
        for (int ks = 0; ks < 4; ++ks)
            LDSM4(fa[ks], aAd + ks*32);
    }
    __syncthreads();   // region A (feat) reads retired before subchunk-1 prefetch overwrites it

    // per-lane B-tile row offset (within a 9216B tile); lanes 16-31 fetch the lo tile
    const uint32_t wrow = (uint32_t)((lane & 7)*ROWB + ((lane >> 3) & 1)*16
                                     + ((lane >> 4) & 1)*9216);
    const int q2 = (lane & 3) * 2;

    float L[8][4];
#pragma unroll
    for (int nt = 0; nt < 8; ++nt)
#pragma unroll
        for (int j = 0; j < 4; ++j) L[nt][j] = 0.f;

    for (int s = 0; s < NSUB; ++s) {
        // prefetch next subchunk into the other region (odd->A, even->B)
        if (s + 1 < NSUB) {
            const unsigned char* src = g_wt + (size_t)(s+1)*36864;
            uint32_t dst = smem_base + (((s+1) & 1) ? REG_A : REG_B);
            for (int i = tid; i < 2304; i += THREADS)
                CPA16(dst + i*16, src + (size_t)i*16);
            CPA_COMMIT();
            asm volatile("cp.async.wait_group 1;" ::: "memory");
        } else {
            asm volatile("cp.async.wait_group 0;" ::: "memory");
        }
        __syncthreads();

        const uint32_t bufb = smem_base + ((s & 1) ? REG_A : REG_B);
        const uint32_t w1b = bufb + wrow;            // hi/lo tile via wrow bit
        const uint32_t w2b = bufb + 2*9216 + wrow;

        // ---- GEMM1: H[16 x 64] = feat_h @ (w1h + w1l) ----
        float Hc[8][4];
#pragma unroll
        for (int nt = 0; nt < 8; ++nt)
#pragma unroll
            for (int j = 0; j < 4; ++j) Hc[nt][j] = 0.f;

#pragma unroll
        for (int ks = 0; ks < 4; ++ks) {
#pragma unroll
            for (int nt = 0; nt < 8; ++nt) {
                uint32_t bf[4];
                LDSM4(bf, w1b + nt*(8*ROWB) + ks*32);   // bf[0,1]=hi frag, bf[2,3]=lo frag
                MMA(Hc[nt], fa[ks], bf[0], bf[1]);
                MMA(Hc[nt], fa[ks], bf[2], bf[3]);
            }
        }

        // ---- GEMM2 interleaved: per k-step g, build fp16 H A-frag then MMA ----
#pragma unroll
        for (int g = 0; g < 4; ++g) {
            uint32_t ha[4];
#pragma unroll
            for (int h = 0; h < 2; ++h) {
                const int t2 = 2*g + h;
                float2 bv = *(float2*)&b1s[s*64 + t2*8 + q2];
                float x0 = fmaxf(Hc[t2][0] + bv.x, 0.f);
                float x1 = fmaxf(Hc[t2][1] + bv.y, 0.f);
                float x2 = fmaxf(Hc[t2][2] + bv.x, 0.f);
                float x3 = fmaxf(Hc[t2][3] + bv.y, 0.f);
                ha[2*h+0] = pack2h(x0, x1);
                ha[2*h+1] = pack2h(x2, x3);
            }
#pragma unroll
            for (int nt = 0; nt < 8; ++nt) {
                uint32_t bf[4];
                LDSM4(bf, w2b + nt*(8*ROWB) + g*32);
                MMA(L[nt], ha, bf[0], bf[1]);
                MMA(L[nt], ha, bf[2], bf[3]);
            }
        }
        __syncthreads();   // retire reads of this buffer before it is overwritten
    }

    // ---- epilogue: +b2, softmax over 64 k (4-lane row groups) ----
#pragma unroll
    for (int nt = 0; nt < 8; ++nt) {
        float2 bv = *(float2*)&b2s[nt*8 + q2];
        L[nt][0] += bv.x; L[nt][1] += bv.y;
        L[nt][2] += bv.x; L[nt][3] += bv.y;
    }
    float mx0 = -1e30f, mx1 = -1e30f;
#pragma unroll
    for (int nt = 0; nt < 8; ++nt) {
        mx0 = fmaxf(mx0, fmaxf(L[nt][0], L[nt][1]));
        mx1 = fmaxf(mx1, fmaxf(L[nt][2], L[nt][3]));
    }
    mx0 = fmaxf(mx0, __shfl_xor_sync(0xffffffffu, mx0, 1));
    mx0 = fmaxf(mx0, __shfl_xor_sync(0xffffffffu, mx0, 2));
    mx1 = fmaxf(mx1, __shfl_xor_sync(0xffffffffu, mx1, 1));
    mx1 = fmaxf(mx1, __shfl_xor_sync(0xffffffffu, mx1, 2));
    float s0 = 0.f, s1 = 0.f;
#pragma unroll
    for (int nt = 0; nt < 8; ++nt) {
        L[nt][0] = __expf(L[nt][0] - mx0); s0 += L[nt][0];
        L[nt][1] = __expf(L[nt][1] - mx0); s0 += L[nt][1];
        L[nt][2] = __expf(L[nt][2] - mx1); s1 += L[nt][2];
        L[nt][3] = __expf(L[nt][3] - mx1); s1 += L[nt][3];
    }
    s0 += __shfl_xor_sync(0xffffffffu, s0, 1);
    s0 += __shfl_xor_sync(0xffffffffu, s0, 2);
    s1 += __shfl_xor_sync(0xffffffffu, s1, 1);
    s1 += __shfl_xor_sync(0xffffffffu, s1, 2);
    const float inv0 = 1.0f / s0, inv1 = 1.0f / s1;

    // ---- mask to SMEM [k][p] in region B (weights consumed) ----
    float* sMask = (float*)(smc + SMASK_OFF);
    __syncthreads();
    {
        const int pr = m0 + (lane >> 2);
#pragma unroll
        for (int nt = 0; nt < 8; ++nt) {
#pragma unroll
            for (int j = 0; j < 2; ++j) {
                int k = nt*8 + q2 + j;
                sMask[k*TP + pr]     = L[nt][j]     * inv0;
                sMask[k*TP + pr + 8] = L[nt][2 + j] * inv1;
            }
        }
    }
    __syncthreads();

    // ---- fp16 mask writeout (b, k, p), half2 packed ----
    __half* gm = g_mask + ((size_t)b * K_) * HW_ + p0;
    for (int idx = tid; idx < K_*64; idx += THREADS) {
        int k = idx >> 6, pi = (idx & 63) * 2;
        __half2 v = __floats2half2_rn(sMask[k*TP + pi], sMask[k*TP + pi + 1]);
        *(__half2*)(gm + (size_t)k * HW_ + pi) = v;
    }

    // ---- per-(b,k) partial reductions ----
    for (int k = wid; k < K_; k += 8) {
        float ss = 0.f, mm = 0.f, a0 = 0.f, a1 = 0.f, a2 = 0.f;
#pragma unroll
        for (int pp = lane; pp < TP; pp += 32) {
            float mval = sMask[k*TP + pp];
            ss += mval;
            mm = fmaxf(mm, mval);
            a0 = fmaf(mval, sImg[pp],        a0);
            a1 = fmaf(mval, sImg[TP + pp],   a1);
            a2 = fmaf(mval, sImg[2*TP + pp], a2);
        }
#pragma unroll
        for (int o = 16; o; o >>= 1) {
            ss += __shfl_down_sync(0xffffffffu, ss, o);
            mm  = fmaxf(mm, __shfl_down_sync(0xffffffffu, mm, o));
            a0 += __shfl_down_sync(0xffffffffu, a0, o);
            a1 += __shfl_down_sync(0xffffffffu, a1, o);
            a2 += __shfl_down_sync(0xffffffffu, a2, o);
        }
        if (lane == 0) {
            atomicAdd(&g_summask[b*K_ + k], ss);
            atomicMax(&g_maxmask[b*K_ + k], __float_as_uint(mm));
            atomicAdd(&g_wc[(b*3 + 0)*K_ + k], a0);
            atomicAdd(&g_wc[(b*3 + 1)*K_ + k], a1);
            atomicAdd(&g_wc[(b*3 + 2)*K_ + k], a2);
        }
    }
}

__global__ void __launch_bounds__(512) finalize_kernel(float* __restrict__ out) {
    __shared__ float sv[512];
    __shared__ float smu[8];
    __shared__ float sstd[8];
    int tid = threadIdx.x;

    float v = g_summask[tid] * (1.0f / (float)HW_);
    sv[tid] = v;
    __syncthreads();
    if (tid < 8) {
        float mu = 0.f;
        for (int k = 0; k < K_; ++k) mu += sv[tid*K_ + k];
        smu[tid] = mu / (float)K_;
    }
    __syncthreads();
    float d = v - smu[tid >> 6];
    sv[tid] = d * d;
    __syncthreads();
    if (tid < 8) {
        float var = 0.f;
        for (int k = 0; k < K_; ++k) var += sv[tid*K_ + k];
        sstd[tid] = sqrtf(var / 63.0f);
    }
    __syncthreads();
    sv[tid] = __uint_as_float(g_maxmask[tid]);
    __syncthreads();
    if (tid == 0) {
        float mm = 0.f;
        for (int i = 0; i < B_*K_; ++i) mm += sv[i];
        out[(size_t)B_*3*HW_ + 0] = mm / (float)(B_*K_);
        float sstdm = 0.f;
        for (int bb = 0; bb < B_; ++bb) sstdm += sstd[bb];
        out[(size_t)B_*3*HW_ + 1] = sstdm / (float)B_;
    }
}

__global__ void __launch_bounds__(256) transform_kernel(float* __restrict__ out) {
    const int b = blockIdx.x >> 8;
    const int p = ((blockIdx.x & 255) << 8) + threadIdx.x;
    __shared__ float swc[3*K_];
    if (threadIdx.x < 3*K_)
        swc[threadIdx.x] = g_wc[b*3*K_ + threadIdx.x] * (1.0f / (float)HW_);
    __syncthreads();

    const __half* mb = g_mask + ((size_t)b * K_) * HW_ + p;
    float t0 = 0.f, t1 = 0.f, t2 = 0.f;
#pragma unroll
    for (int k = 0; k < K_; ++k) {
        float m = __half2float(mb[(size_t)k * HW_]);
        t0 = fmaf(m, swc[k],        t0);
        t1 = fmaf(m, swc[K_ + k],   t1);
        t2 = fmaf(m, swc[2*K_ + k], t2);
    }
    size_t ob = ((size_t)b * 3) * HW_ + p;
    out[ob]         = t0;
    out[ob + HW_]   = t1;
    out[ob + 2*HW_] = t2;
}

extern "C" void kernel_launch(void* const* d_in, const int* in_sizes, int n_in,
                              void* d_out, int out_size) {
    const float* img  = (const float*)d_in[0];
    const float* feat = (const float*)d_in[1];
    // d_in[2] = coord_map (unused by reference)
    const float* w1 = (const float*)d_in[3];
    const float* b1 = (const float*)d_in[4];
    const float* w2 = (const float*)d_in[5];
    const float* b2 = (const float*)d_in[6];
    float* out = (float*)d_out;

    cudaFuncSetAttribute(mask_kernel,
                         cudaFuncAttributeMaxDynamicSharedMemorySize, SMEM_BYTES);

    prep_kernel<<<256, 256>>>(w1, w2);
    zero_kernel<<<6, 256>>>();
    mask_kernel<<<(B_*HW_)/TP, THREADS, SMEM_BYTES>>>(img, feat, b1, b2);
    finalize_kernel<<<1, 512>>>(out);
    transform_kernel<<<(B_*HW_)/256, 256>>>(out);
}